// round 16
// baseline (speedup 1.0000x reference)
#include <cuda_runtime.h>
#include <cstdint>

#define DT_C    0.054f
#define GAMMA_C 4.9f
#define EPS_C   4.8f

constexpr int Bn = 64, Tn = 1024, In = 256, Hn = 512;
constexpr int WROW = In + 2 * Hn;     // 1280 floats per W row
constexpr int NG   = 8;               // batch groups
constexpr int GC   = 16;              // CTAs per group
constexpr int PS   = 1028;            // weight smem pitch (floats)
constexpr int PS4  = PS / 4;
constexpr int SPS  = 516;             // staging pitch (floats)
constexpr int SPS4 = SPS / 4;         // 129
constexpr int SCT  = 512;
constexpr int RP   = 528;             // red pitch per slice (floats)

// Tagged hz state: word = (epoch<<32) | float_bits(hz), accessed ONLY with
// ld/st.relaxed.gpu (morally strong -> guaranteed 8B single-copy atomicity;
// weak .cg 64b stores tear at 32b granularity — root cause of R7/R14).
// Both buffers zeroed every launch.
__device__ __align__(16) unsigned long long g_hz2[2][Bn][Hn];

// ---------------------------------------------------------------------------
// GEMM (+ embedded init: zero BOTH tagged buffers): out[m,h] = X·Wx^T + b
// ---------------------------------------------------------------------------
__global__ void __launch_bounds__(256) cornn_gemm_kernel(
    const float* __restrict__ X, const float* __restrict__ Wg,
    const float* __restrict__ bias, float* __restrict__ out)
{
    if (blockIdx.y == 0 && blockIdx.x < 128) {
        ((ulonglong2*)&g_hz2[0][0][0])[blockIdx.x * 256 + threadIdx.x] =
            make_ulonglong2(0ull, 0ull);
    }

    constexpr int BM = 128, BN = 64, BK = 16, NCH = In / BK;
    __shared__ __align__(16) float As[2][BK][BM + 4];
    __shared__ __align__(16) float Bs[2][BK][BN + 4];

    const int tid = threadIdx.x;
    const int m0 = blockIdx.x * BM;
    const int n0 = blockIdx.y * BN;
    const int tx = tid & 15;
    const int ty = tid >> 4;

    const int rowA0 = tid >> 2,         kqA0 = tid & 3;
    const int rowA1 = (tid + 256) >> 2, kqA1 = tid & 3;
    const int rowB = tid >> 2, kqB = tid & 3;

    const float4* X4 = (const float4*)X;
    const float4* W4 = (const float4*)Wg;

    unsigned long long acc[4][4];
#pragma unroll
    for (int i = 0; i < 4; i++)
#pragma unroll
        for (int j = 0; j < 4; j++) acc[i][j] = 0ull;

    float4 a0 = X4[(size_t)(m0 + rowA0) * 64 + kqA0];
    float4 a1 = X4[(size_t)(m0 + rowA1) * 64 + kqA1];
    float4 bb = W4[(size_t)(n0 + rowB) * 320 + kqB];
#pragma unroll
    for (int cc = 0; cc < 4; cc++) {
        As[0][kqA0 * 4 + cc][rowA0] = ((const float*)&a0)[cc];
        As[0][kqA1 * 4 + cc][rowA1] = ((const float*)&a1)[cc];
        Bs[0][kqB * 4 + cc][rowB]   = ((const float*)&bb)[cc];
    }
    __syncthreads();

    for (int kc = 0; kc < NCH; ++kc) {
        const int cur = kc & 1;
        float4 nA0, nA1, nB;
        if (kc + 1 < NCH) {
            nA0 = X4[(size_t)(m0 + rowA0) * 64 + (kc + 1) * 4 + kqA0];
            nA1 = X4[(size_t)(m0 + rowA1) * 64 + (kc + 1) * 4 + kqA1];
            nB  = W4[(size_t)(n0 + rowB) * 320 + (kc + 1) * 4 + kqB];
        }
#pragma unroll
        for (int kk = 0; kk < BK; ++kk) {
            const ulonglong2* ap = (const ulonglong2*)&As[cur][kk][ty * 8];
            ulonglong2 amA = ap[0];
            ulonglong2 amB = ap[1];
            float4 bv = *(const float4*)&Bs[cur][kk][tx * 4];
            unsigned long long bs[4];
            asm("mov.b64 %0,{%1,%1};" : "=l"(bs[0]) : "f"(bv.x));
            asm("mov.b64 %0,{%1,%1};" : "=l"(bs[1]) : "f"(bv.y));
            asm("mov.b64 %0,{%1,%1};" : "=l"(bs[2]) : "f"(bv.z));
            asm("mov.b64 %0,{%1,%1};" : "=l"(bs[3]) : "f"(bv.w));
            const unsigned long long am[4] = {amA.x, amA.y, amB.x, amB.y};
#pragma unroll
            for (int ip = 0; ip < 4; ip++)
#pragma unroll
                for (int j = 0; j < 4; j++)
                    asm("fma.rn.f32x2 %0,%1,%2,%0;"
                        : "+l"(acc[ip][j]) : "l"(am[ip]), "l"(bs[j]));
        }
        if (kc + 1 < NCH) {
            const int nxt = cur ^ 1;
#pragma unroll
            for (int cc = 0; cc < 4; cc++) {
                As[nxt][kqA0 * 4 + cc][rowA0] = ((const float*)&nA0)[cc];
                As[nxt][kqA1 * 4 + cc][rowA1] = ((const float*)&nA1)[cc];
                Bs[nxt][kqB * 4 + cc][rowB]   = ((const float*)&nB)[cc];
            }
            __syncthreads();
        }
    }

    float4 bv = *(const float4*)&bias[n0 + tx * 4];
#pragma unroll
    for (int ip = 0; ip < 4; ip++) {
        float lo[4], hi[4];
#pragma unroll
        for (int j = 0; j < 4; j++)
            asm("mov.b64 {%0,%1},%2;" : "=f"(lo[j]), "=f"(hi[j]) : "l"(acc[ip][j]));
        float4 o0, o1;
        o0.x = lo[0] + bv.x; o0.y = lo[1] + bv.y; o0.z = lo[2] + bv.z; o0.w = lo[3] + bv.w;
        o1.x = hi[0] + bv.x; o1.y = hi[1] + bv.y; o1.z = hi[2] + bv.z; o1.w = hi[3] + bv.w;
        *(float4*)&out[(size_t)(m0 + ty * 8 + 2 * ip)     * Hn + n0 + tx * 4] = o0;
        *(float4*)&out[(size_t)(m0 + ty * 8 + 2 * ip + 1) * Hn + n0 + tx * 4] = o1;
    }
}

// ---------------------------------------------------------------------------
// Persistent scan (R9 compute, tagged exchange via RELAXED atomics):
// 128 CTAs (8x16), 512 thr. Consumers poll tagged hz words (tag == t);
// producers publish (t+1)-tagged words with st.relaxed.gpu.
// No flags, no release/acquire, no fence. 2 syncthreads/step.
// u-register trick: u = hy·Wy carried incrementally; only hz exchanged.
// ---------------------------------------------------------------------------
__global__ void __launch_bounds__(SCT, 1) cornn_scan_kernel(
    const float* __restrict__ Wg, float* out)
{
    extern __shared__ float smem[];
    float*  Wsm  = smem;                       // 32 rows * PS  (Wz|Wy per row)
    float4* Wsm4 = (float4*)Wsm;
    float*  Ssm  = smem + 32 * PS;             // staging: 8 rows * SPS (hz only)
    float*  red  = Ssm + 8 * SPS;              // 32 slices * RP

    const int tid  = threadIdx.x;
    const int g    = blockIdx.x >> 4;
    const int c    = blockIdx.x & 15;
    const int hbase = c * 32;
    const int bbase = g * 8;

    const int tile = tid & 15;
    const int kq   = tid >> 4;          // 0..31
    const int kp   = kq & 15;           // k-part 0..15
    const int zy   = kq >> 4;           // 0 = Wz half, 1 = Wy half
    const int bt   = tile & 1;
    const int ht   = tile >> 1;

    // ---- resident weight slice (once), rows permuted a -> (a>>2)+(a&3)*8 ----
    {
        const float4* W4 = (const float4*)Wg;
        const int col = tid & 255;
        const int half = tid >> 8;
#pragma unroll
        for (int jj = 0; jj < 16; ++jj) {
            int a = half * 16 + jj;
            int rs = (a >> 2) + (a & 3) * 8;
            Wsm4[rs * PS4 + col] = W4[(size_t)(hbase + a) * (WROW / 4) + (In / 4) + col];
        }
    }
    __syncthreads();

    const unsigned s_sbase =
        (unsigned)__cvta_generic_to_shared(Ssm) + (unsigned)(bt * 4 * SPS * 4) + kp * 16;
    const unsigned s_wbase =
        (unsigned)__cvta_generic_to_shared(Wsm) + (unsigned)(ht * PS * 4)
        + (unsigned)(zy * 2048) + kp * 16;
    const unsigned s_red = (unsigned)__cvta_generic_to_shared(red);

    // output ownership for tid < 256
    const int p_o    = tid >> 4;
    const int tile_o = tid & 15;
    const int bfin = bbase + (tile_o & 1) * 4 + (p_o >> 2);
    const int hfin = hbase + (tile_o >> 1) * 4 + (p_o & 3);
    float hz = 0.0f, hy = 0.0f, u = 0.0f;
    const size_t obase = (size_t)bfin * Tn * Hn + hfin;

    float xs_next = (tid < 256) ? __ldcg(&out[obase]) : 0.0f;

    for (int t = 0; t < Tn; ++t) {
        const float xsv = xs_next;
        const unsigned want = (unsigned)t;

        // ---- poll-load the tagged hz slab (4096 u64, 8/thread) -> smem ----
        const unsigned long long* Sg = &g_hz2[t & 1][bbase][0];
        unsigned long long e[8];
#pragma unroll
        for (int j = 0; j < 8; ++j)
            asm volatile("ld.relaxed.gpu.global.u64 %0,[%1];"
                         : "=l"(e[j]) : "l"(Sg + tid + 512 * j));
#pragma unroll
        for (int j = 0; j < 8; ++j) {
            while ((unsigned)(e[j] >> 32) != want) {
                asm volatile("ld.relaxed.gpu.global.u64 %0,[%1];"
                             : "=l"(e[j]) : "l"(Sg + tid + 512 * j));
            }
        }
#pragma unroll
        for (int j = 0; j < 8; ++j) {
            const int ee  = tid + 512 * j;
            Ssm[(ee >> 9) * SPS + (ee & 511)] = __uint_as_float((unsigned)e[j]);
        }
        __syncthreads();

        // ---- 4x4 packed-f32x2 dot over hz (k=512), this thread's half zy ----
        unsigned long long a[4][4];
#pragma unroll
        for (int i = 0; i < 4; i++)
#pragma unroll
            for (int j = 0; j < 4; j++) a[i][j] = 0ull;

        unsigned sa = s_sbase, wa = s_wbase;
#pragma unroll 2
        for (int it = 0; it < 8; ++it) {
            unsigned long long s01[4], s23[4], w01[4], w23[4];
#pragma unroll
            for (int i = 0; i < 4; i++)
                asm volatile("ld.shared.v2.u64 {%0,%1},[%2];"
                             : "=l"(s01[i]), "=l"(s23[i])
                             : "r"(sa + i * (SPS * 4)));
#pragma unroll
            for (int j = 0; j < 4; j++)
                asm volatile("ld.shared.v2.u64 {%0,%1},[%2];"
                             : "=l"(w01[j]), "=l"(w23[j])
                             : "r"(wa + j * (8 * PS * 4)));
#pragma unroll
            for (int i = 0; i < 4; i++)
#pragma unroll
                for (int j = 0; j < 4; j++) {
                    asm("fma.rn.f32x2 %0,%1,%2,%0;"
                        : "+l"(a[i][j]) : "l"(s01[i]), "l"(w01[j]));
                    asm("fma.rn.f32x2 %0,%1,%2,%0;"
                        : "+l"(a[i][j]) : "l"(s23[i]), "l"(w23[j]));
                }
            sa += 256;   // 16 quads * 16B
            wa += 256;
        }

        // ---- write 16 partials: red[(zy*16+p)*RP + kp*16 + tile] ----
#pragma unroll
        for (int i = 0; i < 4; i++)
#pragma unroll
            for (int j = 0; j < 4; j++) {
                float lo, hi;
                asm("mov.b64 {%0,%1},%2;" : "=f"(lo), "=f"(hi) : "l"(a[i][j]));
                float pv = lo + hi;
                int p = i * 4 + j;
                asm volatile("st.shared.f32 [%0],%1;"
                             :: "r"(s_red + (unsigned)(((zy * 16 + p) * RP
                                                        + kp * 16 + tile) * 4)),
                                "f"(pv));
            }
        __syncthreads();

        if (tid < 256) {
            // ---- reduce dz (slice p_o) and dy (slice 16+p_o) ----
            const unsigned rz = s_red + (unsigned)((p_o * RP + tile_o) * 4);
            const unsigned ry = s_red + (unsigned)(((16 + p_o) * RP + tile_o) * 4);
            float z0r = 0.f, z1r = 0.f, y0r = 0.f, y1r = 0.f;
#pragma unroll
            for (int k = 0; k < 16; k += 2) {
                float az0, az1, ay0, ay1;
                asm volatile("ld.shared.f32 %0,[%1];" : "=f"(az0) : "r"(rz + (k + 0) * 64));
                asm volatile("ld.shared.f32 %0,[%1];" : "=f"(az1) : "r"(rz + (k + 1) * 64));
                asm volatile("ld.shared.f32 %0,[%1];" : "=f"(ay0) : "r"(ry + (k + 0) * 64));
                asm volatile("ld.shared.f32 %0,[%1];" : "=f"(ay1) : "r"(ry + (k + 1) * 64));
                z0r += az0; z1r += az1; y0r += ay0; y1r += ay1;
            }
            const float dz = z0r + z1r;
            const float dy = y0r + y1r;

            u = fmaf(DT_C, dy, u);            // u = hy_{t-1}·Wy
            const float pre = xsv + dz + u;
            const float th = tanhf(pre);
            hz = hz + DT_C * (th - GAMMA_C * hy - EPS_C * hz);
            hy = fmaf(DT_C, hz, hy);

            // publish tagged hz for step t+1 (relaxed atomic 8B word)
            const unsigned long long pz =
                (((unsigned long long)(t + 1)) << 32)
                | (unsigned long long)__float_as_uint(hz);
            asm volatile("st.relaxed.gpu.global.u64 [%0],%1;"
                         :: "l"(&g_hz2[(t + 1) & 1][bfin][hfin]), "l"(pz)
                         : "memory");

            // visible output + next xs prefetch (overlap the next poll)
            out[obase + (size_t)t * Hn] = hy;
            if (t + 1 < Tn) xs_next = __ldcg(&out[obase + (size_t)(t + 1) * Hn]);
        }
        // no sync here: next poll reads global only; Ssm/red hazards are
        // gated by the two barriers above.
    }

    // h_out (1, B, H)
    if (tid < 256)
        out[(size_t)Bn * Tn * Hn + (size_t)bfin * Hn + hfin] = hy;
}

// ---------------------------------------------------------------------------
extern "C" void kernel_launch(void* const* d_in, const int* in_sizes, int n_in,
                              void* d_out, int out_size)
{
    const float* x    = (const float*)d_in[0];
    const float* W    = (const float*)d_in[1];
    const float* bias = (const float*)d_in[2];
    float* out = (float*)d_out;

    const int scan_smem = (32 * PS + 8 * SPS + 32 * RP) * 4;   // 215680 bytes
    cudaFuncSetAttribute(cornn_scan_kernel,
                         cudaFuncAttributeMaxDynamicSharedMemorySize, scan_smem);

    cornn_gemm_kernel<<<dim3((Bn * Tn) / 128, Hn / 64), 256>>>(x, W, bias, out);
    cornn_scan_kernel<<<NG * GC, SCT, scan_smem>>>(W, out);
}

// round 17
// speedup vs baseline: 1.2544x; 1.2544x over previous
#include <cuda_runtime.h>
#include <cstdint>

#define DT_C    0.054f
#define GAMMA_C 4.9f
#define EPS_C   4.8f

constexpr int Bn = 64, Tn = 1024, In = 256, Hn = 512;
constexpr int WROW = In + 2 * Hn;     // 1280 floats per W row
constexpr int NG   = 8;               // batch groups
constexpr int GC   = 16;              // CTAs per group
constexpr int PS   = 1028;            // weight smem pitch (floats)
constexpr int PS4  = PS / 4;
constexpr int SPS  = 516;             // staging pitch (floats)
constexpr int SPS4 = SPS / 4;         // 129
constexpr int SCT  = 512;
constexpr int RP   = 528;             // red pitch per slice (floats)

// hz-only double-buffered state + per-CTA epoch flags (128B apart).
__device__ __align__(16) float g_hz[2][Bn][Hn];
__device__ __align__(128) unsigned int g_flags[NG][GC * 32];

// ---------------------------------------------------------------------------
// GEMM (+ embedded init): out[m,h] = X[m,:]·W[h,:256] + b[h]
// ---------------------------------------------------------------------------
__global__ void __launch_bounds__(256) cornn_gemm_kernel(
    const float* __restrict__ X, const float* __restrict__ Wg,
    const float* __restrict__ bias, float* __restrict__ out)
{
    if (blockIdx.y == 0 && blockIdx.x < 32) {
        ((float4*)&g_hz[0][0][0])[blockIdx.x * 256 + threadIdx.x] =
            make_float4(0.f, 0.f, 0.f, 0.f);
    }
    if (blockIdx.y == 1 && blockIdx.x < 16) {
        (&g_flags[0][0])[blockIdx.x * 256 + threadIdx.x] = 0u;
    }

    constexpr int BM = 128, BN = 64, BK = 16, NCH = In / BK;
    __shared__ __align__(16) float As[2][BK][BM + 4];
    __shared__ __align__(16) float Bs[2][BK][BN + 4];

    const int tid = threadIdx.x;
    const int m0 = blockIdx.x * BM;
    const int n0 = blockIdx.y * BN;
    const int tx = tid & 15;
    const int ty = tid >> 4;

    const int rowA0 = tid >> 2,         kqA0 = tid & 3;
    const int rowA1 = (tid + 256) >> 2, kqA1 = tid & 3;
    const int rowB = tid >> 2, kqB = tid & 3;

    const float4* X4 = (const float4*)X;
    const float4* W4 = (const float4*)Wg;

    unsigned long long acc[4][4];
#pragma unroll
    for (int i = 0; i < 4; i++)
#pragma unroll
        for (int j = 0; j < 4; j++) acc[i][j] = 0ull;

    float4 a0 = X4[(size_t)(m0 + rowA0) * 64 + kqA0];
    float4 a1 = X4[(size_t)(m0 + rowA1) * 64 + kqA1];
    float4 bb = W4[(size_t)(n0 + rowB) * 320 + kqB];
#pragma unroll
    for (int cc = 0; cc < 4; cc++) {
        As[0][kqA0 * 4 + cc][rowA0] = ((const float*)&a0)[cc];
        As[0][kqA1 * 4 + cc][rowA1] = ((const float*)&a1)[cc];
        Bs[0][kqB * 4 + cc][rowB]   = ((const float*)&bb)[cc];
    }
    __syncthreads();

    for (int kc = 0; kc < NCH; ++kc) {
        const int cur = kc & 1;
        float4 nA0, nA1, nB;
        if (kc + 1 < NCH) {
            nA0 = X4[(size_t)(m0 + rowA0) * 64 + (kc + 1) * 4 + kqA0];
            nA1 = X4[(size_t)(m0 + rowA1) * 64 + (kc + 1) * 4 + kqA1];
            nB  = W4[(size_t)(n0 + rowB) * 320 + (kc + 1) * 4 + kqB];
        }
#pragma unroll
        for (int kk = 0; kk < BK; ++kk) {
            const ulonglong2* ap = (const ulonglong2*)&As[cur][kk][ty * 8];
            ulonglong2 amA = ap[0];
            ulonglong2 amB = ap[1];
            float4 bv = *(const float4*)&Bs[cur][kk][tx * 4];
            unsigned long long bs[4];
            asm("mov.b64 %0,{%1,%1};" : "=l"(bs[0]) : "f"(bv.x));
            asm("mov.b64 %0,{%1,%1};" : "=l"(bs[1]) : "f"(bv.y));
            asm("mov.b64 %0,{%1,%1};" : "=l"(bs[2]) : "f"(bv.z));
            asm("mov.b64 %0,{%1,%1};" : "=l"(bs[3]) : "f"(bv.w));
            const unsigned long long am[4] = {amA.x, amA.y, amB.x, amB.y};
#pragma unroll
            for (int ip = 0; ip < 4; ip++)
#pragma unroll
                for (int j = 0; j < 4; j++)
                    asm("fma.rn.f32x2 %0,%1,%2,%0;"
                        : "+l"(acc[ip][j]) : "l"(am[ip]), "l"(bs[j]));
        }
        if (kc + 1 < NCH) {
            const int nxt = cur ^ 1;
#pragma unroll
            for (int cc = 0; cc < 4; cc++) {
                As[nxt][kqA0 * 4 + cc][rowA0] = ((const float*)&nA0)[cc];
                As[nxt][kqA1 * 4 + cc][rowA1] = ((const float*)&nA1)[cc];
                Bs[nxt][kqB * 4 + cc][rowB]   = ((const float*)&nB)[cc];
            }
            __syncthreads();
        }
    }

    float4 bv = *(const float4*)&bias[n0 + tx * 4];
#pragma unroll
    for (int ip = 0; ip < 4; ip++) {
        float lo[4], hi[4];
#pragma unroll
        for (int j = 0; j < 4; j++)
            asm("mov.b64 {%0,%1},%2;" : "=f"(lo[j]), "=f"(hi[j]) : "l"(acc[ip][j]));
        float4 o0, o1;
        o0.x = lo[0] + bv.x; o0.y = lo[1] + bv.y; o0.z = lo[2] + bv.z; o0.w = lo[3] + bv.w;
        o1.x = hi[0] + bv.x; o1.y = hi[1] + bv.y; o1.z = hi[2] + bv.z; o1.w = hi[3] + bv.w;
        *(float4*)&out[(size_t)(m0 + ty * 8 + 2 * ip)     * Hn + n0 + tx * 4] = o0;
        *(float4*)&out[(size_t)(m0 + ty * 8 + 2 * ip + 1) * Hn + n0 + tx * 4] = o1;
    }
}

// ---------------------------------------------------------------------------
// Persistent scan (R9, proven best): 128 CTAs (8 groups x 16), 512 threads.
// u-register trick: only hz exchanged; u = hy·Wy carried incrementally
// (u += DT*dy). Thread = (tile=tid&15, kq=tid>>4): kp=kq&15 (k-part), zy=kq>>4
// (Wz vs Wy half; uniform per warp). Epoch-flag barrier (no fence;
// bar.sync-fence -> st.release.gpu chain).
// ---------------------------------------------------------------------------
__global__ void __launch_bounds__(SCT, 1) cornn_scan_kernel(
    const float* __restrict__ Wg, float* out)
{
    extern __shared__ float smem[];
    float*  Wsm  = smem;                       // 32 rows * PS  (Wz|Wy per row)
    float4* Wsm4 = (float4*)Wsm;
    float*  Ssm  = smem + 32 * PS;             // staging: 8 rows * SPS (hz only)
    float4* Ssm4 = (float4*)Ssm;
    float*  red  = Ssm + 8 * SPS;              // 32 slices * RP

    const int tid  = threadIdx.x;
    const int g    = blockIdx.x >> 4;
    const int c    = blockIdx.x & 15;
    const int hbase = c * 32;
    const int bbase = g * 8;

    const int tile = tid & 15;
    const int kq   = tid >> 4;          // 0..31
    const int kp   = kq & 15;           // k-part 0..15
    const int zy   = kq >> 4;           // 0 = Wz half, 1 = Wy half
    const int bt   = tile & 1;
    const int ht   = tile >> 1;

    // ---- resident weight slice (once), rows permuted a -> (a>>2)+(a&3)*8 ----
    {
        const float4* W4 = (const float4*)Wg;
        const int col = tid & 255;
        const int half = tid >> 8;
#pragma unroll
        for (int jj = 0; jj < 16; ++jj) {
            int a = half * 16 + jj;
            int rs = (a >> 2) + (a & 3) * 8;
            Wsm4[rs * PS4 + col] = W4[(size_t)(hbase + a) * (WROW / 4) + (In / 4) + col];
        }
    }
    __syncthreads();

    const unsigned s_sbase =
        (unsigned)__cvta_generic_to_shared(Ssm) + (unsigned)(bt * 4 * SPS * 4) + kp * 16;
    const unsigned s_wbase =
        (unsigned)__cvta_generic_to_shared(Wsm) + (unsigned)(ht * PS * 4)
        + (unsigned)(zy * 2048) + kp * 16;
    const unsigned s_red = (unsigned)__cvta_generic_to_shared(red);

    // output ownership for tid < 256
    const int p_o    = tid >> 4;
    const int tile_o = tid & 15;
    const int bfin = bbase + (tile_o & 1) * 4 + (p_o >> 2);
    const int hfin = hbase + (tile_o >> 1) * 4 + (p_o & 3);
    float hz = 0.0f, hy = 0.0f, u = 0.0f;
    const size_t obase = (size_t)bfin * Tn * Hn + hfin;

    unsigned int* const my_slot   = &g_flags[g][c * 32];
    unsigned int* const poll_slot = &g_flags[g][(tid < GC ? tid : 0) * 32];

    // staging: 1024 float4 total, 2 per thread
    const int si0 = tid, si1 = tid + 512;

    float xs_next = (tid < 256) ? __ldcg(&out[obase]) : 0.0f;

    for (int t = 0; t < Tn; ++t) {
        const float xsv = xs_next;

        // ---- stage hz slab (8 rows x 512) L2 -> smem ----
        const float4* Hz4 = (const float4*)&g_hz[t & 1][bbase][0];   // 1024 f4
        float4 z0 = __ldcg(Hz4 + si0);
        float4 z1 = __ldcg(Hz4 + si1);
        Ssm4[(si0 >> 7) * SPS4 + (si0 & 127)] = z0;
        Ssm4[(si1 >> 7) * SPS4 + (si1 & 127)] = z1;
        __syncthreads();

        // ---- 4x4 packed-f32x2 dot over hz (k=512), this thread's half zy ----
        unsigned long long a[4][4];
#pragma unroll
        for (int i = 0; i < 4; i++)
#pragma unroll
            for (int j = 0; j < 4; j++) a[i][j] = 0ull;

        unsigned sa = s_sbase, wa = s_wbase;
#pragma unroll 2
        for (int it = 0; it < 8; ++it) {
            unsigned long long s01[4], s23[4], w01[4], w23[4];
#pragma unroll
            for (int i = 0; i < 4; i++)
                asm volatile("ld.shared.v2.u64 {%0,%1},[%2];"
                             : "=l"(s01[i]), "=l"(s23[i])
                             : "r"(sa + i * (SPS * 4)));
#pragma unroll
            for (int j = 0; j < 4; j++)
                asm volatile("ld.shared.v2.u64 {%0,%1},[%2];"
                             : "=l"(w01[j]), "=l"(w23[j])
                             : "r"(wa + j * (8 * PS * 4)));
#pragma unroll
            for (int i = 0; i < 4; i++)
#pragma unroll
                for (int j = 0; j < 4; j++) {
                    asm("fma.rn.f32x2 %0,%1,%2,%0;"
                        : "+l"(a[i][j]) : "l"(s01[i]), "l"(w01[j]));
                    asm("fma.rn.f32x2 %0,%1,%2,%0;"
                        : "+l"(a[i][j]) : "l"(s23[i]), "l"(w23[j]));
                }
            sa += 256;   // 16 quads * 16B
            wa += 256;
        }

        // ---- write 16 partials: red[(zy*16+p)*RP + kp*16 + tile] ----
#pragma unroll
        for (int i = 0; i < 4; i++)
#pragma unroll
            for (int j = 0; j < 4; j++) {
                float lo, hi;
                asm("mov.b64 {%0,%1},%2;" : "=f"(lo), "=f"(hi) : "l"(a[i][j]));
                float pv = lo + hi;
                int p = i * 4 + j;
                asm volatile("st.shared.f32 [%0],%1;"
                             :: "r"(s_red + (unsigned)(((zy * 16 + p) * RP
                                                        + kp * 16 + tile) * 4)),
                                "f"(pv));
            }
        __syncthreads();

        if (tid < 256) {
            // ---- reduce dz (slice p_o) and dy (slice 16+p_o) ----
            const unsigned rz = s_red + (unsigned)((p_o * RP + tile_o) * 4);
            const unsigned ry = s_red + (unsigned)(((16 + p_o) * RP + tile_o) * 4);
            float z0r = 0.f, z1r = 0.f, y0r = 0.f, y1r = 0.f;
#pragma unroll
            for (int k = 0; k < 16; k += 2) {
                float az0, az1, ay0, ay1;
                asm volatile("ld.shared.f32 %0,[%1];" : "=f"(az0) : "r"(rz + (k + 0) * 64));
                asm volatile("ld.shared.f32 %0,[%1];" : "=f"(az1) : "r"(rz + (k + 1) * 64));
                asm volatile("ld.shared.f32 %0,[%1];" : "=f"(ay0) : "r"(ry + (k + 0) * 64));
                asm volatile("ld.shared.f32 %0,[%1];" : "=f"(ay1) : "r"(ry + (k + 1) * 64));
                z0r += az0; z1r += az1; y0r += ay0; y1r += ay1;
            }
            const float dz = z0r + z1r;
            const float dy = y0r + y1r;

            u = fmaf(DT_C, dy, u);            // u = hy_{t-1}·Wy
            const float pre = xsv + dz + u;
            const float th = tanhf(pre);
            hz = hz + DT_C * (th - GAMMA_C * hy - EPS_C * hz);
            hy = fmaf(DT_C, hz, hy);

            // publish hz only
            __stcg(&g_hz[(t + 1) & 1][bfin][hfin], hz);
        }

        __syncthreads();                 // all hz publishes issued (cta fence)
        if (tid == 0) {
            asm volatile("st.release.gpu.global.u32 [%0],%1;"
                         :: "l"(my_slot), "r"((unsigned)(t + 1)) : "memory");
        }

        // overlap with the poll: visible output + next xs prefetch
        if (tid < 256) {
            out[obase + (size_t)t * Hn] = hy;
            if (t + 1 < Tn) xs_next = __ldcg(&out[obase + (size_t)(t + 1) * Hn]);
        }

        if (tid < GC) {
            bool mine = false;
            unsigned vv;
            do {
                if (!mine) {
                    asm volatile("ld.acquire.gpu.global.u32 %0,[%1];"
                                 : "=r"(vv) : "l"(poll_slot));
                    mine = (vv >= (unsigned)(t + 1));
                }
            } while (__ballot_sync(0x0000ffffu, mine) != 0x0000ffffu);
        }
        __syncthreads();
    }

    // h_out (1, B, H)
    if (tid < 256)
        out[(size_t)Bn * Tn * Hn + (size_t)bfin * Hn + hfin] = hy;
}

// ---------------------------------------------------------------------------
extern "C" void kernel_launch(void* const* d_in, const int* in_sizes, int n_in,
                              void* d_out, int out_size)
{
    const float* x    = (const float*)d_in[0];
    const float* W    = (const float*)d_in[1];
    const float* bias = (const float*)d_in[2];
    float* out = (float*)d_out;

    const int scan_smem = (32 * PS + 8 * SPS + 32 * RP) * 4;   // 215680 bytes
    cudaFuncSetAttribute(cornn_scan_kernel,
                         cudaFuncAttributeMaxDynamicSharedMemorySize, scan_smem);

    cornn_gemm_kernel<<<dim3((Bn * Tn) / 128, Hn / 64), 256>>>(x, W, bias, out);
    cornn_scan_kernel<<<NG * GC, SCT, scan_smem>>>(W, out);
}